// round 5
// baseline (speedup 1.0000x reference)
#include <cuda_runtime.h>
#include <cuda_bf16.h>
#include <math.h>
#include <stdint.h>

#define B_SZ  2
#define S_LEN 2048
#define D_DIM 1024
#define H_NUM 16
#define DKH   64
#define MTOT  (B_SZ * S_LEN)          // 4096

// ---------------------------------------------------------------------------
// Scratch (allocation-free rule: __device__ globals). All bf16 hi/lo splits.
// ---------------------------------------------------------------------------
__device__ __nv_bfloat16 g_sQh[MTOT * D_DIM], g_sQl[MTOT * D_DIM];  // split(query)
__device__ __nv_bfloat16 g_sKh[MTOT * D_DIM], g_sKl[MTOT * D_DIM];  // split(key)
__device__ __nv_bfloat16 g_sVh[MTOT * D_DIM], g_sVl[MTOT * D_DIM];  // split(value)
__device__ __nv_bfloat16 g_wqh[D_DIM * D_DIM], g_wql[D_DIM * D_DIM];
__device__ __nv_bfloat16 g_wkh[D_DIM * D_DIM], g_wkl[D_DIM * D_DIM];
__device__ __nv_bfloat16 g_wvh[D_DIM * D_DIM], g_wvl[D_DIM * D_DIM];
__device__ __nv_bfloat16 g_woh[D_DIM * D_DIM], g_wol[D_DIM * D_DIM];
__device__ __nv_bfloat16 g_Qh[MTOT * D_DIM], g_Ql[MTOT * D_DIM];    // proj outputs
__device__ __nv_bfloat16 g_Kh[MTOT * D_DIM], g_Kl[MTOT * D_DIM];
__device__ __nv_bfloat16 g_Vh[MTOT * D_DIM], g_Vl[MTOT * D_DIM];
__device__ __nv_bfloat16 g_Xh[MTOT * D_DIM], g_Xl[MTOT * D_DIM];    // attn output

// ===========================================================================
// helpers (baseline ISA: ldmatrix sm_75+, mma.sync bf16 + cp.async sm_80+)
// ===========================================================================
__device__ __forceinline__ uint32_t smem_u32(const void* p) {
    uint32_t a;
    asm("{ .reg .u64 t; cvta.to.shared.u64 t, %1; cvt.u32.u64 %0, t; }"
        : "=r"(a) : "l"(p));
    return a;
}
__device__ __forceinline__ void ldmx4(uint32_t* r, uint32_t addr) {
    asm volatile("ldmatrix.sync.aligned.m8n8.x4.shared.b16 {%0,%1,%2,%3}, [%4];"
                 : "=r"(r[0]), "=r"(r[1]), "=r"(r[2]), "=r"(r[3]) : "r"(addr));
}
__device__ __forceinline__ void ldmx4t(uint32_t* r, uint32_t addr) {
    asm volatile("ldmatrix.sync.aligned.m8n8.x4.trans.shared.b16 {%0,%1,%2,%3}, [%4];"
                 : "=r"(r[0]), "=r"(r[1]), "=r"(r[2]), "=r"(r[3]) : "r"(addr));
}
__device__ __forceinline__ void mma16816(float* c, const uint32_t* a,
                                         uint32_t b0, uint32_t b1) {
    asm volatile(
        "mma.sync.aligned.m16n8k16.row.col.f32.bf16.bf16.f32 "
        "{%0,%1,%2,%3}, {%4,%5,%6,%7}, {%8,%9}, {%0,%1,%2,%3};"
        : "+f"(c[0]), "+f"(c[1]), "+f"(c[2]), "+f"(c[3])
        : "r"(a[0]), "r"(a[1]), "r"(a[2]), "r"(a[3]), "r"(b0), "r"(b1));
}
__device__ __forceinline__ uint32_t packbf(float x, float y) {
    __nv_bfloat162 h = __float22bfloat162_rn(make_float2(x, y));
    return *(uint32_t*)&h;
}
__device__ __forceinline__ void split2(float x, float y, uint32_t& h, uint32_t& l) {
    h = packbf(x, y);
    __nv_bfloat162 t = *(__nv_bfloat162*)&h;
    float2 f = __bfloat1622float2(t);
    l = packbf(x - f.x, y - f.y);
}
__device__ __forceinline__ void cpasync16(uint32_t dst, const void* src) {
    asm volatile("cp.async.cg.shared.global [%0], [%1], 16;"
                 :: "r"(dst), "l"(src));
}
__device__ __forceinline__ void cp_commit() {
    asm volatile("cp.async.commit_group;" ::: "memory");
}
__device__ __forceinline__ void cp_wait0() {
    asm volatile("cp.async.wait_group 0;" ::: "memory");
}
__device__ __forceinline__ void cp_wait1() {
    asm volatile("cp.async.wait_group 1;" ::: "memory");
}

// ===========================================================================
// convert_split: f32 -> bf16 hi/lo (grid-stride, float4 vectorized)
// ===========================================================================
__global__ void convert_split(const float4* __restrict__ x,
                              uint2* __restrict__ hi, uint2* __restrict__ lo,
                              int n4)
{
    const int stride = gridDim.x * blockDim.x;
    for (int i = blockIdx.x * blockDim.x + threadIdx.x; i < n4; i += stride) {
        const float4 v = x[i];
        uint2 uh, ul;
        split2(v.x, v.y, uh.x, ul.x);
        split2(v.z, v.w, uh.y, ul.y);
        hi[i] = uh;
        lo[i] = ul;
    }
}

// ===========================================================================
// GEMM (NT): C[M,N] = A[M,K] @ W[N,K]^T from pre-split bf16 hi/lo operands.
// CTA 128x128, K staged 64 at a time, cp.async double-buffered (2 stages).
// 8 warps: warp_m = wid&1, warp_n = wid>>1; per-warp 4x4 m16n8 tiles.
// mode: Cf != nullptr -> f32 output; else split bf16 output (Ch/Cl).
// ===========================================================================
constexpr int SASB    = 144;               // padded row bytes (64 bf16 + 8 pad)
constexpr int GT      = 128 * SASB;        // 18432 bytes per 128-row tile
constexpr int GSTAGE  = 4 * GT;            // 73728 per pipeline stage
constexpr int SM_GEMM_TOTAL = 2 * GSTAGE;  // 147456
constexpr int STAGES  = D_DIM / 64;        // 16

__global__ __launch_bounds__(256, 1)
void gemm_mma(const __nv_bfloat16* __restrict__ Ah, const __nv_bfloat16* __restrict__ Al,
              const __nv_bfloat16* __restrict__ Bh, const __nv_bfloat16* __restrict__ Bl,
              float* __restrict__ Cf,
              __nv_bfloat16* __restrict__ Ch, __nv_bfloat16* __restrict__ Cl,
              int M, int N, int K)
{
    extern __shared__ char smc[];
    const uint32_t sb = smem_u32(smc);
    const int tid  = threadIdx.x;
    const int wid  = tid >> 5;
    const int lane = tid & 31;
    const int warp_m = wid & 1;
    const int warp_n = wid >> 1;
    const int m0 = blockIdx.y * 128;
    const int n0 = blockIdx.x * 128;

    float acc[4][4][4];
#pragma unroll
    for (int mi = 0; mi < 4; mi++)
#pragma unroll
        for (int ni = 0; ni < 4; ni++)
#pragma unroll
            for (int q = 0; q < 4; q++) acc[mi][ni][q] = 0.f;

    const __nv_bfloat16* bases[4] = {Ah + (size_t)m0 * K, Al + (size_t)m0 * K,
                                     Bh + (size_t)n0 * K, Bl + (size_t)n0 * K};
    const int prow = tid >> 3;       // 0..31 row sub-index
    const int pch  = tid & 7;        // 16B chunk within row

    // producer: stage s -> buffer (s&1). 16 cp.async per thread.
    auto produce = [&](int s) {
        const uint32_t bufb = sb + (s & 1) * GSTAGE;
#pragma unroll
        for (int i = 0; i < 16; i++) {
            const int t   = i >> 2;                 // tile 0..3
            const int row = ((i & 3) << 5) | prow;  // 0..127
            const void* src = bases[t] + (size_t)row * K + s * 64 + pch * 8;
            cpasync16(bufb + t * GT + row * SASB + pch * 16, src);
        }
    };

    const int lr  = lane & 15;
    const int lkb = (lane >> 4) << 4;

    produce(0);
    cp_commit();

    for (int s = 0; s < STAGES; s++) {
        if (s + 1 < STAGES) {
            produce(s + 1);
            cp_commit();
            cp_wait1();
        } else {
            cp_wait0();
        }
        __syncthreads();

        const uint32_t bufb = sb + (s & 1) * GSTAGE;
#pragma unroll
        for (int ks = 0; ks < 4; ks++) {
            const uint32_t kb = ks * 32 + lkb;
            uint32_t ah[4][4], al[4][4];
#pragma unroll
            for (int mi = 0; mi < 4; mi++) {
                const uint32_t byte = (warp_m * 64 + mi * 16 + lr) * SASB + kb;
                ldmx4(ah[mi], bufb + byte);
                ldmx4(al[mi], bufb + GT + byte);
            }
            uint32_t bh[4][2], bl[4][2];
#pragma unroll
            for (int nb = 0; nb < 2; nb++) {
                const uint32_t byte = (warp_n * 32 + nb * 16 + lr) * SASB + kb;
                uint32_t r[4];
                ldmx4(r, bufb + 2 * GT + byte);
                bh[nb * 2][0] = r[0]; bh[nb * 2 + 1][0] = r[1];
                bh[nb * 2][1] = r[2]; bh[nb * 2 + 1][1] = r[3];
                ldmx4(r, bufb + 3 * GT + byte);
                bl[nb * 2][0] = r[0]; bl[nb * 2 + 1][0] = r[1];
                bl[nb * 2][1] = r[2]; bl[nb * 2 + 1][1] = r[3];
            }
#pragma unroll
            for (int mi = 0; mi < 4; mi++)
#pragma unroll
                for (int ni = 0; ni < 4; ni++) {
                    mma16816(acc[mi][ni], ah[mi], bh[ni][0], bh[ni][1]);
                    mma16816(acc[mi][ni], ah[mi], bl[ni][0], bl[ni][1]);
                    mma16816(acc[mi][ni], al[mi], bh[ni][0], bh[ni][1]);
                }
        }
        __syncthreads();
    }

    // ---- epilogue ----
    const int er = lane >> 2;
    const int ec = (lane & 3) * 2;
    if (Cf) {
#pragma unroll
        for (int mi = 0; mi < 4; mi++)
#pragma unroll
            for (int ni = 0; ni < 4; ni++) {
                const int r = m0 + warp_m * 64 + mi * 16 + er;
                const int c = n0 + warp_n * 32 + ni * 8 + ec;
                *(float2*)(Cf + (size_t)r * N + c) =
                    make_float2(acc[mi][ni][0], acc[mi][ni][1]);
                *(float2*)(Cf + (size_t)(r + 8) * N + c) =
                    make_float2(acc[mi][ni][2], acc[mi][ni][3]);
            }
    } else {
#pragma unroll
        for (int mi = 0; mi < 4; mi++)
#pragma unroll
            for (int ni = 0; ni < 4; ni++) {
                const int r = m0 + warp_m * 64 + mi * 16 + er;
                const int c = n0 + warp_n * 32 + ni * 8 + ec;
                uint32_t h, l;
                split2(acc[mi][ni][0], acc[mi][ni][1], h, l);
                *(uint32_t*)(Ch + (size_t)r * N + c) = h;
                *(uint32_t*)(Cl + (size_t)r * N + c) = l;
                split2(acc[mi][ni][2], acc[mi][ni][3], h, l);
                *(uint32_t*)(Ch + (size_t)(r + 8) * N + c) = h;
                *(uint32_t*)(Cl + (size_t)(r + 8) * N + c) = l;
            }
    }
}

// ===========================================================================
// Tensor-core flash attention (causal), pre-split bf16 inputs via cp.async.
// CTA = 128 q-rows x (b,h). 8 warps; K/V blocks of 64, double-buffered.
// Output written as split bf16 (Xh/Xl) for the final GEMM.
// ===========================================================================
constexpr int FQHI = 0;
constexpr int FQLO = FQHI + GT;            // 18432
constexpr int FKV0 = FQLO + GT;            // 36864: KV buffer 0
constexpr int KVT  = 64 * SASB;            // 9216 per 64-row tile
constexpr int KVBUF = 4 * KVT;             // 36864 (Khi,Klo,Vhi,Vlo)
constexpr int FSM_TOTAL = FKV0 + 2 * KVBUF;  // 110592

__global__ __launch_bounds__(256, 1)
void flash_mma(const __nv_bfloat16* __restrict__ Qh, const __nv_bfloat16* __restrict__ Ql,
               const __nv_bfloat16* __restrict__ Kh, const __nv_bfloat16* __restrict__ Kl,
               const __nv_bfloat16* __restrict__ Vh, const __nv_bfloat16* __restrict__ Vl,
               __nv_bfloat16* __restrict__ Xh, __nv_bfloat16* __restrict__ Xl)
{
    extern __shared__ char smc[];
    const uint32_t sb = smem_u32(smc);
    const int tid  = threadIdx.x;
    const int wid  = tid >> 5;
    const int lane = tid & 31;
    const int qb   = gridDim.x - 1 - blockIdx.x;   // longest blocks first
    const int h    = blockIdx.y;
    const int b    = blockIdx.z;

    const size_t head = (size_t)b * S_LEN * D_DIM + (size_t)h * DKH;
    const int prow = tid >> 3;
    const int pch  = tid & 7;

    // ---- Q tile: 2 x (128 rows x 128B), 8 cp.async per thread ----
    {
        const __nv_bfloat16* qb_[2] = {Qh + head, Ql + head};
#pragma unroll
        for (int i = 0; i < 8; i++) {
            const int t   = i >> 2;
            const int row = ((i & 3) << 5) | prow;
            const void* src = qb_[t] + (size_t)(qb * 128 + row) * D_DIM + pch * 8;
            cpasync16(sb + t * GT + row * SASB + pch * 16, src);
        }
    }

    const __nv_bfloat16* kvb[4] = {Kh + head, Kl + head, Vh + head, Vl + head};
    auto produce_kv = [&](int kb) {
        const uint32_t bufb = sb + FKV0 + (kb & 1) * KVBUF;
#pragma unroll
        for (int i = 0; i < 8; i++) {
            const int t   = i >> 1;                 // 0=Khi,1=Klo,2=Vhi,3=Vlo
            const int row = ((i & 1) << 5) | prow;  // 0..63
            const void* src = kvb[t] + (size_t)(kb * 64 + row) * D_DIM + pch * 8;
            cpasync16(bufb + t * KVT + row * SASB + pch * 16, src);
        }
    };

    produce_kv(0);
    cp_commit();   // group: Q + KV(0)

    float o[8][4];
    float m0r = -1e30f, m1r = -1e30f, l0r = 0.f, l1r = 0.f;
#pragma unroll
    for (int ni = 0; ni < 8; ni++)
#pragma unroll
        for (int q = 0; q < 4; q++) o[ni][q] = 0.f;

    const int lr  = lane & 15;
    const int lkb = (lane >> 4) << 4;
    const int kb_max = 2 * qb + 1;

    for (int kb = 0; kb <= kb_max; kb++) {
        if (kb < kb_max) {
            produce_kv(kb + 1);
            cp_commit();
            cp_wait1();
        } else {
            cp_wait0();
        }
        __syncthreads();

        const uint32_t kvbase = sb + FKV0 + (kb & 1) * KVBUF;

        // ---- QK^T ----
        float sc[8][4];
#pragma unroll
        for (int ni = 0; ni < 8; ni++)
#pragma unroll
            for (int q = 0; q < 4; q++) sc[ni][q] = 0.f;

#pragma unroll
        for (int ks = 0; ks < 4; ks++) {
            const uint32_t abyte = (wid * 16 + lr) * SASB + ks * 32 + lkb;
            uint32_t qh[4], ql[4];
            ldmx4(qh, sb + FQHI + abyte);
            ldmx4(ql, sb + FQLO + abyte);
#pragma unroll
            for (int nb = 0; nb < 4; nb++) {
                const uint32_t bbyte = (nb * 16 + lr) * SASB + ks * 32 + lkb;
                uint32_t kh[4], kl[4];
                ldmx4(kh, kvbase + bbyte);
                ldmx4(kl, kvbase + KVT + bbyte);
                mma16816(sc[nb * 2],     qh, kh[0], kh[2]);
                mma16816(sc[nb * 2],     qh, kl[0], kl[2]);
                mma16816(sc[nb * 2],     ql, kh[0], kh[2]);
                mma16816(sc[nb * 2 + 1], qh, kh[1], kh[3]);
                mma16816(sc[nb * 2 + 1], qh, kl[1], kl[3]);
                mma16816(sc[nb * 2 + 1], ql, kh[1], kh[3]);
            }
        }

        // ---- scale (1/sqrt(dk)) ----
#pragma unroll
        for (int ni = 0; ni < 8; ni++)
#pragma unroll
            for (int q = 0; q < 4; q++) sc[ni][q] *= 0.125f;

        // ---- causal mask ----
        const int q0 = qb * 128 + wid * 16 + (lane >> 2);
        if (kb * 64 + 63 > qb * 128 + wid * 16) {
#pragma unroll
            for (int ni = 0; ni < 8; ni++) {
#pragma unroll
                for (int c = 0; c < 2; c++) {
                    const int col = kb * 64 + ni * 8 + (lane & 3) * 2 + c;
                    if (col > q0)     sc[ni][c]     = -1e30f;
                    if (col > q0 + 8) sc[ni][2 + c] = -1e30f;
                }
            }
        }

        // ---- online softmax ----
        float mx0 = -1e30f, mx1 = -1e30f;
#pragma unroll
        for (int ni = 0; ni < 8; ni++) {
            mx0 = fmaxf(mx0, fmaxf(sc[ni][0], sc[ni][1]));
            mx1 = fmaxf(mx1, fmaxf(sc[ni][2], sc[ni][3]));
        }
        mx0 = fmaxf(mx0, __shfl_xor_sync(0xffffffffu, mx0, 1));
        mx0 = fmaxf(mx0, __shfl_xor_sync(0xffffffffu, mx0, 2));
        mx1 = fmaxf(mx1, __shfl_xor_sync(0xffffffffu, mx1, 1));
        mx1 = fmaxf(mx1, __shfl_xor_sync(0xffffffffu, mx1, 2));

        const float mn0 = fmaxf(m0r, mx0);
        const float mn1 = fmaxf(m1r, mx1);
        const float al0 = __expf(m0r - mn0);
        const float al1 = __expf(m1r - mn1);
        m0r = mn0; m1r = mn1;

        float ls0 = 0.f, ls1 = 0.f;
#pragma unroll
        for (int ni = 0; ni < 8; ni++) {
            sc[ni][0] = __expf(sc[ni][0] - mn0); ls0 += sc[ni][0];
            sc[ni][1] = __expf(sc[ni][1] - mn0); ls0 += sc[ni][1];
            sc[ni][2] = __expf(sc[ni][2] - mn1); ls1 += sc[ni][2];
            sc[ni][3] = __expf(sc[ni][3] - mn1); ls1 += sc[ni][3];
        }
        ls0 += __shfl_xor_sync(0xffffffffu, ls0, 1);
        ls0 += __shfl_xor_sync(0xffffffffu, ls0, 2);
        ls1 += __shfl_xor_sync(0xffffffffu, ls1, 1);
        ls1 += __shfl_xor_sync(0xffffffffu, ls1, 2);
        l0r = l0r * al0 + ls0;
        l1r = l1r * al1 + ls1;
#pragma unroll
        for (int ni = 0; ni < 8; ni++) {
            o[ni][0] *= al0; o[ni][1] *= al0;
            o[ni][2] *= al1; o[ni][3] *= al1;
        }

        // ---- P.V ----
#pragma unroll
        for (int ks = 0; ks < 4; ks++) {
            uint32_t ph[4], pl[4];
            split2(sc[2 * ks][0],     sc[2 * ks][1],     ph[0], pl[0]);
            split2(sc[2 * ks][2],     sc[2 * ks][3],     ph[1], pl[1]);
            split2(sc[2 * ks + 1][0], sc[2 * ks + 1][1], ph[2], pl[2]);
            split2(sc[2 * ks + 1][2], sc[2 * ks + 1][3], ph[3], pl[3]);
#pragma unroll
            for (int nt = 0; nt < 4; nt++) {
                const uint32_t vbyte =
                    (ks * 16 + ((lane >> 3) & 1) * 8 + (lane & 7)) * SASB +
                    nt * 32 + ((lane >> 4) << 4);
                uint32_t vh[4], vl[4];
                ldmx4t(vh, kvbase + 2 * KVT + vbyte);
                ldmx4t(vl, kvbase + 3 * KVT + vbyte);
                mma16816(o[nt * 2],     ph, vh[0], vh[1]);
                mma16816(o[nt * 2],     ph, vl[0], vl[1]);
                mma16816(o[nt * 2],     pl, vh[0], vh[1]);
                mma16816(o[nt * 2 + 1], ph, vh[2], vh[3]);
                mma16816(o[nt * 2 + 1], ph, vl[2], vl[3]);
                mma16816(o[nt * 2 + 1], pl, vh[2], vh[3]);
            }
        }
        __syncthreads();
    }

    // ---- epilogue: split bf16 write ----
    const float inv0 = 1.f / l0r;
    const float inv1 = 1.f / l1r;
    const int r0 = qb * 128 + wid * 16 + (lane >> 2);
    const int ec = (lane & 3) * 2;
#pragma unroll
    for (int ni = 0; ni < 8; ni++) {
        const size_t c = head + (size_t)ni * 8 + ec;
        uint32_t hh, ll;
        split2(o[ni][0] * inv0, o[ni][1] * inv0, hh, ll);
        *(uint32_t*)(Xh + c + (size_t)r0 * D_DIM) = hh;
        *(uint32_t*)(Xl + c + (size_t)r0 * D_DIM) = ll;
        split2(o[ni][2] * inv1, o[ni][3] * inv1, hh, ll);
        *(uint32_t*)(Xh + c + (size_t)(r0 + 8) * D_DIM) = hh;
        *(uint32_t*)(Xl + c + (size_t)(r0 + 8) * D_DIM) = ll;
    }
}

// ---------------------------------------------------------------------------
// launch
// ---------------------------------------------------------------------------
extern "C" void kernel_launch(void* const* d_in, const int* in_sizes, int n_in,
                              void* d_out, int out_size)
{
    const float* query = (const float*)d_in[0];
    const float* key   = (const float*)d_in[1];
    const float* value = (const float*)d_in[2];
    const float* Wq    = (const float*)d_in[3];
    const float* Wk    = (const float*)d_in[4];
    const float* Wv    = (const float*)d_in[5];
    const float* Wo    = (const float*)d_in[6];
    float* out = (float*)d_out;

    __nv_bfloat16 *sQh, *sQl, *sKh, *sKl, *sVh, *sVl;
    __nv_bfloat16 *wqh, *wql, *wkh, *wkl, *wvh, *wvl, *woh, *wol;
    __nv_bfloat16 *Qh, *Ql, *Kh, *Kl, *Vh, *Vl, *Xh, *Xl;
    cudaGetSymbolAddress((void**)&sQh, g_sQh); cudaGetSymbolAddress((void**)&sQl, g_sQl);
    cudaGetSymbolAddress((void**)&sKh, g_sKh); cudaGetSymbolAddress((void**)&sKl, g_sKl);
    cudaGetSymbolAddress((void**)&sVh, g_sVh); cudaGetSymbolAddress((void**)&sVl, g_sVl);
    cudaGetSymbolAddress((void**)&wqh, g_wqh); cudaGetSymbolAddress((void**)&wql, g_wql);
    cudaGetSymbolAddress((void**)&wkh, g_wkh); cudaGetSymbolAddress((void**)&wkl, g_wkl);
    cudaGetSymbolAddress((void**)&wvh, g_wvh); cudaGetSymbolAddress((void**)&wvl, g_wvl);
    cudaGetSymbolAddress((void**)&woh, g_woh); cudaGetSymbolAddress((void**)&wol, g_wol);
    cudaGetSymbolAddress((void**)&Qh, g_Qh);   cudaGetSymbolAddress((void**)&Ql, g_Ql);
    cudaGetSymbolAddress((void**)&Kh, g_Kh);   cudaGetSymbolAddress((void**)&Kl, g_Kl);
    cudaGetSymbolAddress((void**)&Vh, g_Vh);   cudaGetSymbolAddress((void**)&Vl, g_Vl);
    cudaGetSymbolAddress((void**)&Xh, g_Xh);   cudaGetSymbolAddress((void**)&Xl, g_Xl);

    const int M = MTOT, N = D_DIM, K = D_DIM;
    const int n4a = M * D_DIM / 4;       // activations
    const int n4w = D_DIM * D_DIM / 4;   // weights

    convert_split<<<512, 256>>>((const float4*)query, (uint2*)sQh, (uint2*)sQl, n4a);
    convert_split<<<512, 256>>>((const float4*)key,   (uint2*)sKh, (uint2*)sKl, n4a);
    convert_split<<<512, 256>>>((const float4*)value, (uint2*)sVh, (uint2*)sVl, n4a);
    convert_split<<<512, 256>>>((const float4*)Wq, (uint2*)wqh, (uint2*)wql, n4w);
    convert_split<<<512, 256>>>((const float4*)Wk, (uint2*)wkh, (uint2*)wkl, n4w);
    convert_split<<<512, 256>>>((const float4*)Wv, (uint2*)wvh, (uint2*)wvl, n4w);
    convert_split<<<512, 256>>>((const float4*)Wo, (uint2*)woh, (uint2*)wol, n4w);

    cudaFuncSetAttribute(gemm_mma, cudaFuncAttributeMaxDynamicSharedMemorySize,
                         SM_GEMM_TOTAL);
    dim3 ggrid(N / 128, M / 128);   // (8, 32)

    gemm_mma<<<ggrid, 256, SM_GEMM_TOTAL>>>(sQh, sQl, wqh, wql, nullptr, Qh, Ql, M, N, K);
    gemm_mma<<<ggrid, 256, SM_GEMM_TOTAL>>>(sKh, sKl, wkh, wkl, nullptr, Kh, Kl, M, N, K);
    gemm_mma<<<ggrid, 256, SM_GEMM_TOTAL>>>(sVh, sVl, wvh, wvl, nullptr, Vh, Vl, M, N, K);

    cudaFuncSetAttribute(flash_mma, cudaFuncAttributeMaxDynamicSharedMemorySize,
                         FSM_TOTAL);
    dim3 fgrid(S_LEN / 128, H_NUM, B_SZ);   // (16, 16, 2)
    flash_mma<<<fgrid, 256, FSM_TOTAL>>>(Qh, Ql, Kh, Kl, Vh, Vl, Xh, Xl);

    gemm_mma<<<ggrid, 256, SM_GEMM_TOTAL>>>(Xh, Xl, woh, wol, out, nullptr, nullptr, M, N, K);
}

// round 6
// speedup vs baseline: 1.4195x; 1.4195x over previous
#include <cuda_runtime.h>
#include <cuda_fp16.h>
#include <math.h>
#include <stdint.h>

#define B_SZ  2
#define S_LEN 2048
#define D_DIM 1024
#define H_NUM 16
#define DKH   64
#define MTOT  (B_SZ * S_LEN)          // 4096

// ---------------------------------------------------------------------------
// Scratch (allocation-free rule: __device__ globals). fp16 operands.
// ---------------------------------------------------------------------------
__device__ __half g_sQh[MTOT * D_DIM], g_sQl[MTOT * D_DIM];  // split(query)
__device__ __half g_sKh[MTOT * D_DIM], g_sKl[MTOT * D_DIM];  // split(key)
__device__ __half g_sVh[MTOT * D_DIM], g_sVl[MTOT * D_DIM];  // split(value)
__device__ __half g_wq[D_DIM * D_DIM], g_wk[D_DIM * D_DIM];  // single fp16 weights
__device__ __half g_wv[D_DIM * D_DIM], g_wo[D_DIM * D_DIM];
__device__ __half g_Qh[MTOT * D_DIM], g_Ql[MTOT * D_DIM];    // Q proj (split)
__device__ __half g_Kv[MTOT * D_DIM];                        // K proj (single)
__device__ __half g_Vv[MTOT * D_DIM];                        // V proj (single)
__device__ __half g_Xh[MTOT * D_DIM], g_Xl[MTOT * D_DIM];    // attn out (split)

// ===========================================================================
// helpers (baseline ISA: ldmatrix sm_75+, mma.sync fp16 + cp.async sm_80+)
// ===========================================================================
__device__ __forceinline__ uint32_t smem_u32(const void* p) {
    uint32_t a;
    asm("{ .reg .u64 t; cvta.to.shared.u64 t, %1; cvt.u32.u64 %0, t; }"
        : "=r"(a) : "l"(p));
    return a;
}
__device__ __forceinline__ void ldmx4(uint32_t* r, uint32_t addr) {
    asm volatile("ldmatrix.sync.aligned.m8n8.x4.shared.b16 {%0,%1,%2,%3}, [%4];"
                 : "=r"(r[0]), "=r"(r[1]), "=r"(r[2]), "=r"(r[3]) : "r"(addr));
}
__device__ __forceinline__ void ldmx4t(uint32_t* r, uint32_t addr) {
    asm volatile("ldmatrix.sync.aligned.m8n8.x4.trans.shared.b16 {%0,%1,%2,%3}, [%4];"
                 : "=r"(r[0]), "=r"(r[1]), "=r"(r[2]), "=r"(r[3]) : "r"(addr));
}
__device__ __forceinline__ void mma16816(float* c, const uint32_t* a,
                                         uint32_t b0, uint32_t b1) {
    asm volatile(
        "mma.sync.aligned.m16n8k16.row.col.f32.f16.f16.f32 "
        "{%0,%1,%2,%3}, {%4,%5,%6,%7}, {%8,%9}, {%0,%1,%2,%3};"
        : "+f"(c[0]), "+f"(c[1]), "+f"(c[2]), "+f"(c[3])
        : "r"(a[0]), "r"(a[1]), "r"(a[2]), "r"(a[3]), "r"(b0), "r"(b1));
}
__device__ __forceinline__ uint32_t packh(float x, float y) {
    __half2 h = __float22half2_rn(make_float2(x, y));
    return *(uint32_t*)&h;
}
__device__ __forceinline__ void split2h(float x, float y, uint32_t& h, uint32_t& l) {
    h = packh(x, y);
    __half2 t = *(__half2*)&h;
    float2 f = __half22float2(t);
    l = packh(x - f.x, y - f.y);
}
__device__ __forceinline__ void cpasync16(uint32_t dst, const void* src) {
    asm volatile("cp.async.cg.shared.global [%0], [%1], 16;"
                 :: "r"(dst), "l"(src));
}
__device__ __forceinline__ void cp_commit() {
    asm volatile("cp.async.commit_group;" ::: "memory");
}
__device__ __forceinline__ void cp_wait0() {
    asm volatile("cp.async.wait_group 0;" ::: "memory");
}
__device__ __forceinline__ void cp_wait1() {
    asm volatile("cp.async.wait_group 1;" ::: "memory");
}

// ===========================================================================
// convert kernels: f32 -> fp16 split (hi/lo) and f32 -> fp16 single
// ===========================================================================
__global__ void convert_split2(const float4* __restrict__ x,
                               uint2* __restrict__ hi, uint2* __restrict__ lo,
                               int n4)
{
    const int stride = gridDim.x * blockDim.x;
    for (int i = blockIdx.x * blockDim.x + threadIdx.x; i < n4; i += stride) {
        const float4 v = x[i];
        uint2 uh, ul;
        split2h(v.x, v.y, uh.x, ul.x);
        split2h(v.z, v.w, uh.y, ul.y);
        hi[i] = uh;
        lo[i] = ul;
    }
}
__global__ void convert_h(const float4* __restrict__ x, uint2* __restrict__ hi, int n4)
{
    const int stride = gridDim.x * blockDim.x;
    for (int i = blockIdx.x * blockDim.x + threadIdx.x; i < n4; i += stride) {
        const float4 v = x[i];
        uint2 uh;
        uh.x = packh(v.x, v.y);
        uh.y = packh(v.z, v.w);
        hi[i] = uh;
    }
}

// ===========================================================================
// GEMM (NT): C[M,N] = A[M,K] @ W[N,K]^T.  A split fp16 (hi+lo), W single fp16.
// C = Ah*W + Al*W  (2 MMAs per tile). CTA 128x128, K staged 64, double-buffer.
// Output modes: Cf -> f32; Cl!=null -> split fp16; else single fp16 (Ch).
// ===========================================================================
constexpr int SASB    = 144;               // padded row bytes (64 fp16 + pad)
constexpr int GT      = 128 * SASB;        // 18432 per 128-row tile
constexpr int GSTAGE  = 3 * GT;            // 55296 per stage (Ahi,Alo,B)
constexpr int SM_GEMM_TOTAL = 2 * GSTAGE;  // 110592
constexpr int STAGES  = D_DIM / 64;        // 16

__global__ __launch_bounds__(256, 1)
void gemm_mma(const __half* __restrict__ Ah, const __half* __restrict__ Al,
              const __half* __restrict__ Bh,
              float* __restrict__ Cf,
              __half* __restrict__ Ch, __half* __restrict__ Cl,
              int M, int N, int K)
{
    extern __shared__ char smc[];
    const uint32_t sb = smem_u32(smc);
    const int tid  = threadIdx.x;
    const int wid  = tid >> 5;
    const int lane = tid & 31;
    const int warp_m = wid & 1;
    const int warp_n = wid >> 1;
    const int m0 = blockIdx.y * 128;
    const int n0 = blockIdx.x * 128;

    float acc[4][4][4];
#pragma unroll
    for (int mi = 0; mi < 4; mi++)
#pragma unroll
        for (int ni = 0; ni < 4; ni++)
#pragma unroll
            for (int q = 0; q < 4; q++) acc[mi][ni][q] = 0.f;

    const __half* bases[3] = {Ah + (size_t)m0 * K, Al + (size_t)m0 * K,
                              Bh + (size_t)n0 * K};
    const int prow = tid >> 3;       // 0..31
    const int pch  = tid & 7;        // 16B chunk within row

    auto produce = [&](int s) {
        const uint32_t bufb = sb + (s & 1) * GSTAGE;
#pragma unroll
        for (int i = 0; i < 12; i++) {
            const int t   = i >> 2;                 // tile 0..2
            const int row = ((i & 3) << 5) | prow;  // 0..127
            const void* src = bases[t] + (size_t)row * K + s * 64 + pch * 8;
            cpasync16(bufb + t * GT + row * SASB + pch * 16, src);
        }
    };

    const int lr  = lane & 15;
    const int lkb = (lane >> 4) << 4;

    produce(0);
    cp_commit();

    for (int s = 0; s < STAGES; s++) {
        if (s + 1 < STAGES) {
            produce(s + 1);
            cp_commit();
            cp_wait1();
        } else {
            cp_wait0();
        }
        __syncthreads();

        const uint32_t bufb = sb + (s & 1) * GSTAGE;
#pragma unroll
        for (int ks = 0; ks < 4; ks++) {
            const uint32_t kb = ks * 32 + lkb;
            uint32_t ah[4][4], al[4][4];
#pragma unroll
            for (int mi = 0; mi < 4; mi++) {
                const uint32_t byte = (warp_m * 64 + mi * 16 + lr) * SASB + kb;
                ldmx4(ah[mi], bufb + byte);
                ldmx4(al[mi], bufb + GT + byte);
            }
            uint32_t bh[4][2];
#pragma unroll
            for (int nb = 0; nb < 2; nb++) {
                const uint32_t byte = (warp_n * 32 + nb * 16 + lr) * SASB + kb;
                uint32_t r[4];
                ldmx4(r, bufb + 2 * GT + byte);
                bh[nb * 2][0] = r[0]; bh[nb * 2 + 1][0] = r[1];
                bh[nb * 2][1] = r[2]; bh[nb * 2 + 1][1] = r[3];
            }
#pragma unroll
            for (int mi = 0; mi < 4; mi++)
#pragma unroll
                for (int ni = 0; ni < 4; ni++) {
                    mma16816(acc[mi][ni], ah[mi], bh[ni][0], bh[ni][1]);
                    mma16816(acc[mi][ni], al[mi], bh[ni][0], bh[ni][1]);
                }
        }
        __syncthreads();
    }

    // ---- epilogue ----
    const int er = lane >> 2;
    const int ec = (lane & 3) * 2;
    if (Cf) {
#pragma unroll
        for (int mi = 0; mi < 4; mi++)
#pragma unroll
            for (int ni = 0; ni < 4; ni++) {
                const int r = m0 + warp_m * 64 + mi * 16 + er;
                const int c = n0 + warp_n * 32 + ni * 8 + ec;
                *(float2*)(Cf + (size_t)r * N + c) =
                    make_float2(acc[mi][ni][0], acc[mi][ni][1]);
                *(float2*)(Cf + (size_t)(r + 8) * N + c) =
                    make_float2(acc[mi][ni][2], acc[mi][ni][3]);
            }
    } else if (Cl) {
#pragma unroll
        for (int mi = 0; mi < 4; mi++)
#pragma unroll
            for (int ni = 0; ni < 4; ni++) {
                const int r = m0 + warp_m * 64 + mi * 16 + er;
                const int c = n0 + warp_n * 32 + ni * 8 + ec;
                uint32_t h, l;
                split2h(acc[mi][ni][0], acc[mi][ni][1], h, l);
                *(uint32_t*)(Ch + (size_t)r * N + c) = h;
                *(uint32_t*)(Cl + (size_t)r * N + c) = l;
                split2h(acc[mi][ni][2], acc[mi][ni][3], h, l);
                *(uint32_t*)(Ch + (size_t)(r + 8) * N + c) = h;
                *(uint32_t*)(Cl + (size_t)(r + 8) * N + c) = l;
            }
    } else {
#pragma unroll
        for (int mi = 0; mi < 4; mi++)
#pragma unroll
            for (int ni = 0; ni < 4; ni++) {
                const int r = m0 + warp_m * 64 + mi * 16 + er;
                const int c = n0 + warp_n * 32 + ni * 8 + ec;
                *(uint32_t*)(Ch + (size_t)r * N + c) =
                    packh(acc[mi][ni][0], acc[mi][ni][1]);
                *(uint32_t*)(Ch + (size_t)(r + 8) * N + c) =
                    packh(acc[mi][ni][2], acc[mi][ni][3]);
            }
    }
}

// ===========================================================================
// Flash attention (causal), fp16 operands. CTA = 128 q-rows x (b,h), 8 warps.
// Q split (hi/lo) resident; K,V single fp16, 64-row blocks, double-buffered.
// QK^T: 2 MMAs/tile (Qh*K + Ql*K). PV: 2 MMAs/tile (Ph*V + Pl*V).
// ===========================================================================
constexpr int FQHI = 0;
constexpr int FQLO = FQHI + GT;            // 18432
constexpr int FKV0 = FQLO + GT;            // 36864
constexpr int KVT  = 64 * SASB;            // 9216 per 64-row tile
constexpr int KVBUF = 2 * KVT;             // 18432 (K, V)
constexpr int FSM_TOTAL = FKV0 + 2 * KVBUF;  // 73728

__global__ __launch_bounds__(256, 1)
void flash_mma(const __half* __restrict__ Qh, const __half* __restrict__ Ql,
               const __half* __restrict__ Kv, const __half* __restrict__ Vv,
               __half* __restrict__ Xh, __half* __restrict__ Xl)
{
    extern __shared__ char smc[];
    const uint32_t sb = smem_u32(smc);
    const int tid  = threadIdx.x;
    const int wid  = tid >> 5;
    const int lane = tid & 31;
    const int qb   = gridDim.x - 1 - blockIdx.x;   // longest blocks first
    const int h    = blockIdx.y;
    const int b    = blockIdx.z;

    const size_t head = (size_t)b * S_LEN * D_DIM + (size_t)h * DKH;
    const int prow = tid >> 3;
    const int pch  = tid & 7;

    // ---- Q tiles (hi, lo): 8 cp.async per thread ----
    {
        const __half* qb_[2] = {Qh + head, Ql + head};
#pragma unroll
        for (int i = 0; i < 8; i++) {
            const int t   = i >> 2;
            const int row = ((i & 3) << 5) | prow;
            const void* src = qb_[t] + (size_t)(qb * 128 + row) * D_DIM + pch * 8;
            cpasync16(sb + t * GT + row * SASB + pch * 16, src);
        }
    }

    const __half* kvb[2] = {Kv + head, Vv + head};
    auto produce_kv = [&](int kb) {
        const uint32_t bufb = sb + FKV0 + (kb & 1) * KVBUF;
#pragma unroll
        for (int i = 0; i < 4; i++) {
            const int t   = i >> 1;                 // 0=K, 1=V
            const int row = ((i & 1) << 5) | prow;  // 0..63
            const void* src = kvb[t] + (size_t)(kb * 64 + row) * D_DIM + pch * 8;
            cpasync16(bufb + t * KVT + row * SASB + pch * 16, src);
        }
    };

    produce_kv(0);
    cp_commit();   // group: Q + KV(0)

    float o[8][4];
    float m0r = -1e30f, m1r = -1e30f, l0r = 0.f, l1r = 0.f;
#pragma unroll
    for (int ni = 0; ni < 8; ni++)
#pragma unroll
        for (int q = 0; q < 4; q++) o[ni][q] = 0.f;

    const int lr  = lane & 15;
    const int lkb = (lane >> 4) << 4;
    const int kb_max = 2 * qb + 1;

    for (int kb = 0; kb <= kb_max; kb++) {
        if (kb < kb_max) {
            produce_kv(kb + 1);
            cp_commit();
            cp_wait1();
        } else {
            cp_wait0();
        }
        __syncthreads();

        const uint32_t kvbase = sb + FKV0 + (kb & 1) * KVBUF;

        // ---- QK^T ----
        float sc[8][4];
#pragma unroll
        for (int ni = 0; ni < 8; ni++)
#pragma unroll
            for (int q = 0; q < 4; q++) sc[ni][q] = 0.f;

#pragma unroll
        for (int ks = 0; ks < 4; ks++) {
            const uint32_t abyte = (wid * 16 + lr) * SASB + ks * 32 + lkb;
            uint32_t qh[4], ql[4];
            ldmx4(qh, sb + FQHI + abyte);
            ldmx4(ql, sb + FQLO + abyte);
#pragma unroll
            for (int nb = 0; nb < 4; nb++) {
                const uint32_t bbyte = (nb * 16 + lr) * SASB + ks * 32 + lkb;
                uint32_t kh[4];
                ldmx4(kh, kvbase + bbyte);
                mma16816(sc[nb * 2],     qh, kh[0], kh[2]);
                mma16816(sc[nb * 2],     ql, kh[0], kh[2]);
                mma16816(sc[nb * 2 + 1], qh, kh[1], kh[3]);
                mma16816(sc[nb * 2 + 1], ql, kh[1], kh[3]);
            }
        }

        // ---- scale (1/sqrt(dk)) ----
#pragma unroll
        for (int ni = 0; ni < 8; ni++)
#pragma unroll
            for (int q = 0; q < 4; q++) sc[ni][q] *= 0.125f;

        // ---- causal mask ----
        const int q0 = qb * 128 + wid * 16 + (lane >> 2);
        if (kb * 64 + 63 > qb * 128 + wid * 16) {
#pragma unroll
            for (int ni = 0; ni < 8; ni++) {
#pragma unroll
                for (int c = 0; c < 2; c++) {
                    const int col = kb * 64 + ni * 8 + (lane & 3) * 2 + c;
                    if (col > q0)     sc[ni][c]     = -1e30f;
                    if (col > q0 + 8) sc[ni][2 + c] = -1e30f;
                }
            }
        }

        // ---- online softmax ----
        float mx0 = -1e30f, mx1 = -1e30f;
#pragma unroll
        for (int ni = 0; ni < 8; ni++) {
            mx0 = fmaxf(mx0, fmaxf(sc[ni][0], sc[ni][1]));
            mx1 = fmaxf(mx1, fmaxf(sc[ni][2], sc[ni][3]));
        }
        mx0 = fmaxf(mx0, __shfl_xor_sync(0xffffffffu, mx0, 1));
        mx0 = fmaxf(mx0, __shfl_xor_sync(0xffffffffu, mx0, 2));
        mx1 = fmaxf(mx1, __shfl_xor_sync(0xffffffffu, mx1, 1));
        mx1 = fmaxf(mx1, __shfl_xor_sync(0xffffffffu, mx1, 2));

        const float mn0 = fmaxf(m0r, mx0);
        const float mn1 = fmaxf(m1r, mx1);
        const float al0 = __expf(m0r - mn0);
        const float al1 = __expf(m1r - mn1);
        m0r = mn0; m1r = mn1;

        float ls0 = 0.f, ls1 = 0.f;
#pragma unroll
        for (int ni = 0; ni < 8; ni++) {
            sc[ni][0] = __expf(sc[ni][0] - mn0); ls0 += sc[ni][0];
            sc[ni][1] = __expf(sc[ni][1] - mn0); ls0 += sc[ni][1];
            sc[ni][2] = __expf(sc[ni][2] - mn1); ls1 += sc[ni][2];
            sc[ni][3] = __expf(sc[ni][3] - mn1); ls1 += sc[ni][3];
        }
        ls0 += __shfl_xor_sync(0xffffffffu, ls0, 1);
        ls0 += __shfl_xor_sync(0xffffffffu, ls0, 2);
        ls1 += __shfl_xor_sync(0xffffffffu, ls1, 1);
        ls1 += __shfl_xor_sync(0xffffffffu, ls1, 2);
        l0r = l0r * al0 + ls0;
        l1r = l1r * al1 + ls1;
#pragma unroll
        for (int ni = 0; ni < 8; ni++) {
            o[ni][0] *= al0; o[ni][1] *= al0;
            o[ni][2] *= al1; o[ni][3] *= al1;
        }

        // ---- P.V ----
#pragma unroll
        for (int ks = 0; ks < 4; ks++) {
            uint32_t ph[4], pl[4];
            split2h(sc[2 * ks][0],     sc[2 * ks][1],     ph[0], pl[0]);
            split2h(sc[2 * ks][2],     sc[2 * ks][3],     ph[1], pl[1]);
            split2h(sc[2 * ks + 1][0], sc[2 * ks + 1][1], ph[2], pl[2]);
            split2h(sc[2 * ks + 1][2], sc[2 * ks + 1][3], ph[3], pl[3]);
#pragma unroll
            for (int nt = 0; nt < 4; nt++) {
                const uint32_t vbyte =
                    (ks * 16 + ((lane >> 3) & 1) * 8 + (lane & 7)) * SASB +
                    nt * 32 + ((lane >> 4) << 4);
                uint32_t vh[4];
                ldmx4t(vh, kvbase + KVT + vbyte);
                mma16816(o[nt * 2],     ph, vh[0], vh[1]);
                mma16816(o[nt * 2],     pl, vh[0], vh[1]);
                mma16816(o[nt * 2 + 1], ph, vh[2], vh[3]);
                mma16816(o[nt * 2 + 1], pl, vh[2], vh[3]);
            }
        }
        __syncthreads();
    }

    // ---- epilogue: split fp16 write ----
    const float inv0 = 1.f / l0r;
    const float inv1 = 1.f / l1r;
    const int r0 = qb * 128 + wid * 16 + (lane >> 2);
    const int ec = (lane & 3) * 2;
#pragma unroll
    for (int ni = 0; ni < 8; ni++) {
        const size_t c = head + (size_t)ni * 8 + ec;
        uint32_t hh, ll;
        split2h(o[ni][0] * inv0, o[ni][1] * inv0, hh, ll);
        *(uint32_t*)(Xh + c + (size_t)r0 * D_DIM) = hh;
        *(uint32_t*)(Xl + c + (size_t)r0 * D_DIM) = ll;
        split2h(o[ni][2] * inv1, o[ni][3] * inv1, hh, ll);
        *(uint32_t*)(Xh + c + (size_t)(r0 + 8) * D_DIM) = hh;
        *(uint32_t*)(Xl + c + (size_t)(r0 + 8) * D_DIM) = ll;
    }
}

// ---------------------------------------------------------------------------
// launch
// ---------------------------------------------------------------------------
extern "C" void kernel_launch(void* const* d_in, const int* in_sizes, int n_in,
                              void* d_out, int out_size)
{
    const float* query = (const float*)d_in[0];
    const float* key   = (const float*)d_in[1];
    const float* value = (const float*)d_in[2];
    const float* Wq    = (const float*)d_in[3];
    const float* Wk    = (const float*)d_in[4];
    const float* Wv    = (const float*)d_in[5];
    const float* Wo    = (const float*)d_in[6];
    float* out = (float*)d_out;

    __half *sQh, *sQl, *sKh, *sKl, *sVh, *sVl;
    __half *wq, *wk, *wv, *wo;
    __half *Qh, *Ql, *Kv, *Vv, *Xh, *Xl;
    cudaGetSymbolAddress((void**)&sQh, g_sQh); cudaGetSymbolAddress((void**)&sQl, g_sQl);
    cudaGetSymbolAddress((void**)&sKh, g_sKh); cudaGetSymbolAddress((void**)&sKl, g_sKl);
    cudaGetSymbolAddress((void**)&sVh, g_sVh); cudaGetSymbolAddress((void**)&sVl, g_sVl);
    cudaGetSymbolAddress((void**)&wq, g_wq);   cudaGetSymbolAddress((void**)&wk, g_wk);
    cudaGetSymbolAddress((void**)&wv, g_wv);   cudaGetSymbolAddress((void**)&wo, g_wo);
    cudaGetSymbolAddress((void**)&Qh, g_Qh);   cudaGetSymbolAddress((void**)&Ql, g_Ql);
    cudaGetSymbolAddress((void**)&Kv, g_Kv);   cudaGetSymbolAddress((void**)&Vv, g_Vv);
    cudaGetSymbolAddress((void**)&Xh, g_Xh);   cudaGetSymbolAddress((void**)&Xl, g_Xl);

    const int M = MTOT, N = D_DIM, K = D_DIM;
    const int n4a = M * D_DIM / 4;
    const int n4w = D_DIM * D_DIM / 4;

    convert_split2<<<512, 256>>>((const float4*)query, (uint2*)sQh, (uint2*)sQl, n4a);
    convert_split2<<<512, 256>>>((const float4*)key,   (uint2*)sKh, (uint2*)sKl, n4a);
    convert_split2<<<512, 256>>>((const float4*)value, (uint2*)sVh, (uint2*)sVl, n4a);
    convert_h<<<512, 256>>>((const float4*)Wq, (uint2*)wq, n4w);
    convert_h<<<512, 256>>>((const float4*)Wk, (uint2*)wk, n4w);
    convert_h<<<512, 256>>>((const float4*)Wv, (uint2*)wv, n4w);
    convert_h<<<512, 256>>>((const float4*)Wo, (uint2*)wo, n4w);

    cudaFuncSetAttribute(gemm_mma, cudaFuncAttributeMaxDynamicSharedMemorySize,
                         SM_GEMM_TOTAL);
    dim3 ggrid(N / 128, M / 128);   // (8, 32)

    // Q: split output; K, V: single fp16 output
    gemm_mma<<<ggrid, 256, SM_GEMM_TOTAL>>>(sQh, sQl, wq, nullptr, Qh, Ql, M, N, K);
    gemm_mma<<<ggrid, 256, SM_GEMM_TOTAL>>>(sKh, sKl, wk, nullptr, Kv, nullptr, M, N, K);
    gemm_mma<<<ggrid, 256, SM_GEMM_TOTAL>>>(sVh, sVl, wv, nullptr, Vv, nullptr, M, N, K);

    cudaFuncSetAttribute(flash_mma, cudaFuncAttributeMaxDynamicSharedMemorySize,
                         FSM_TOTAL);
    dim3 fgrid(S_LEN / 128, H_NUM, B_SZ);   // (16, 16, 2)
    flash_mma<<<fgrid, 256, FSM_TOTAL>>>(Qh, Ql, Kv, Vv, Xh, Xl);

    gemm_mma<<<ggrid, 256, SM_GEMM_TOTAL>>>(Xh, Xl, wo, out, nullptr, nullptr, M, N, K);
}

// round 7
// speedup vs baseline: 1.4746x; 1.0388x over previous
#include <cuda_runtime.h>
#include <cuda_fp16.h>
#include <math.h>
#include <stdint.h>

#define B_SZ  2
#define S_LEN 2048
#define D_DIM 1024
#define H_NUM 16
#define DKH   64
#define MTOT  (B_SZ * S_LEN)          // 4096

// ---------------------------------------------------------------------------
// Scratch (allocation-free rule: __device__ globals). fp16 operands.
// ---------------------------------------------------------------------------
__device__ __half g_Qh[MTOT * D_DIM], g_Ql[MTOT * D_DIM];    // Q proj (split)
__device__ __half g_Kv[MTOT * D_DIM];                        // K proj (single)
__device__ __half g_Vv[MTOT * D_DIM];                        // V proj (single)
__device__ __half g_Xh[MTOT * D_DIM], g_Xl[MTOT * D_DIM];    // attn out (split)

// ===========================================================================
// helpers (baseline ISA: ldmatrix sm_75+, mma.sync fp16 + cp.async sm_80+)
// ===========================================================================
__device__ __forceinline__ uint32_t smem_u32(const void* p) {
    uint32_t a;
    asm("{ .reg .u64 t; cvta.to.shared.u64 t, %1; cvt.u32.u64 %0, t; }"
        : "=r"(a) : "l"(p));
    return a;
}
__device__ __forceinline__ void ldmx4(uint32_t* r, uint32_t addr) {
    asm volatile("ldmatrix.sync.aligned.m8n8.x4.shared.b16 {%0,%1,%2,%3}, [%4];"
                 : "=r"(r[0]), "=r"(r[1]), "=r"(r[2]), "=r"(r[3]) : "r"(addr));
}
__device__ __forceinline__ void ldmx4t(uint32_t* r, uint32_t addr) {
    asm volatile("ldmatrix.sync.aligned.m8n8.x4.trans.shared.b16 {%0,%1,%2,%3}, [%4];"
                 : "=r"(r[0]), "=r"(r[1]), "=r"(r[2]), "=r"(r[3]) : "r"(addr));
}
__device__ __forceinline__ void mma16816(float* c, const uint32_t* a,
                                         uint32_t b0, uint32_t b1) {
    asm volatile(
        "mma.sync.aligned.m16n8k16.row.col.f32.f16.f16.f32 "
        "{%0,%1,%2,%3}, {%4,%5,%6,%7}, {%8,%9}, {%0,%1,%2,%3};"
        : "+f"(c[0]), "+f"(c[1]), "+f"(c[2]), "+f"(c[3])
        : "r"(a[0]), "r"(a[1]), "r"(a[2]), "r"(a[3]), "r"(b0), "r"(b1));
}
__device__ __forceinline__ uint32_t packh(float x, float y) {
    __half2 h = __float22half2_rn(make_float2(x, y));
    return *(uint32_t*)&h;
}
__device__ __forceinline__ void split2h(float x, float y, uint32_t& h, uint32_t& l) {
    h = packh(x, y);
    __half2 t = *(__half2*)&h;
    float2 f = __half22float2(t);
    l = packh(x - f.x, y - f.y);
}
__device__ __forceinline__ void cpasync16(uint32_t dst, const void* src) {
    asm volatile("cp.async.cg.shared.global [%0], [%1], 16;"
                 :: "r"(dst), "l"(src));
}
__device__ __forceinline__ void cp_commit() {
    asm volatile("cp.async.commit_group;" ::: "memory");
}
__device__ __forceinline__ void cp_wait0() {
    asm volatile("cp.async.wait_group 0;" ::: "memory");
}
__device__ __forceinline__ void cp_wait1() {
    asm volatile("cp.async.wait_group 1;" ::: "memory");
}

// ===========================================================================
// Shared GEMM geometry
// ===========================================================================
constexpr int SASB    = 144;               // padded row bytes (64 fp16 + pad)
constexpr int GT      = 128 * SASB;        // 18432 per 128-row tile
constexpr int GSTAGE  = 3 * GT;            // 55296 per stage (Ahi,Alo,B)
constexpr int SM_GEMM_TOTAL = 2 * GSTAGE;  // 110592
constexpr int STAGES  = D_DIM / 64;        // 16

// ---------------------------------------------------------------------------
// mainloop compute for one 64-K stage (shared by both GEMM kernels)
// ---------------------------------------------------------------------------
__device__ __forceinline__ void gemm_stage_compute(
    uint32_t bufb, int warp_m, int warp_n, int lr, int lkb, float acc[4][4][4])
{
#pragma unroll
    for (int ks = 0; ks < 4; ks++) {
        const uint32_t kb = ks * 32 + lkb;
        uint32_t ah[4][4], al[4][4];
#pragma unroll
        for (int mi = 0; mi < 4; mi++) {
            const uint32_t byte = (warp_m * 64 + mi * 16 + lr) * SASB + kb;
            ldmx4(ah[mi], bufb + byte);
            ldmx4(al[mi], bufb + GT + byte);
        }
        uint32_t bh[4][2];
#pragma unroll
        for (int nb = 0; nb < 2; nb++) {
            const uint32_t byte = (warp_n * 32 + nb * 16 + lr) * SASB + kb;
            uint32_t r[4];
            ldmx4(r, bufb + 2 * GT + byte);
            bh[nb * 2][0] = r[0]; bh[nb * 2 + 1][0] = r[1];
            bh[nb * 2][1] = r[2]; bh[nb * 2 + 1][1] = r[3];
        }
#pragma unroll
        for (int mi = 0; mi < 4; mi++)
#pragma unroll
            for (int ni = 0; ni < 4; ni++) {
                mma16816(acc[mi][ni], ah[mi], bh[ni][0], bh[ni][1]);
                mma16816(acc[mi][ni], al[mi], bh[ni][0], bh[ni][1]);
            }
    }
}

// ===========================================================================
// gemm_proj: z=0: Q=query@Wq^T (split out), z=1: K (single), z=2: V (single).
// A,W are f32; producer converts/splits to fp16 smem in-kernel.
// ===========================================================================
__global__ __launch_bounds__(256, 1)
void gemm_proj(const float* __restrict__ Aq, const float* __restrict__ Ak,
               const float* __restrict__ Av,
               const float* __restrict__ Wq, const float* __restrict__ Wk,
               const float* __restrict__ Wv,
               __half* __restrict__ Qh, __half* __restrict__ Ql,
               __half* __restrict__ Kv, __half* __restrict__ Vv)
{
    extern __shared__ char smc[];
    const uint32_t sb = smem_u32(smc);
    const int tid  = threadIdx.x;
    const int wid  = tid >> 5;
    const int lane = tid & 31;
    const int warp_m = wid & 1;
    const int warp_n = wid >> 1;
    const int m0 = blockIdx.y * 128;
    const int n0 = blockIdx.x * 128;
    const int z  = blockIdx.z;
    const int K  = D_DIM, N = D_DIM;

    const float* A = (z == 0) ? Aq : (z == 1) ? Ak : Av;
    const float* W = (z == 0) ? Wq : (z == 1) ? Wk : Wv;
    const float* Abase = A + (size_t)m0 * K;
    const float* Wbase = W + (size_t)n0 * K;

    float acc[4][4][4];
#pragma unroll
    for (int mi = 0; mi < 4; mi++)
#pragma unroll
        for (int ni = 0; ni < 4; ni++)
#pragma unroll
            for (int q = 0; q < 4; q++) acc[mi][ni][q] = 0.f;

    const int lr  = lane & 15;
    const int lkb = (lane >> 4) << 4;

    float4 pa[8], pw[8];
    auto load_regs = [&](int s) {
#pragma unroll
        for (int i = 0; i < 8; i++) {
            const int c = i * 256 + tid;
            const int row = c >> 4, ch = c & 15;
            pa[i] = *(const float4*)(Abase + (size_t)row * K + s * 64 + ch * 4);
            pw[i] = *(const float4*)(Wbase + (size_t)row * K + s * 64 + ch * 4);
        }
    };
    auto store_regs = [&](uint32_t bufo) {
        char* hi_p = smc + bufo;
        char* lo_p = smc + bufo + GT;
        char* b_p  = smc + bufo + 2 * GT;
#pragma unroll
        for (int i = 0; i < 8; i++) {
            const int c = i * 256 + tid;
            const int row = c >> 4, ch = c & 15;
            const uint32_t off = row * SASB + ch * 8;
            uint32_t h0, l0, h1, l1;
            split2h(pa[i].x, pa[i].y, h0, l0);
            split2h(pa[i].z, pa[i].w, h1, l1);
            *(uint2*)(hi_p + off) = make_uint2(h0, h1);
            *(uint2*)(lo_p + off) = make_uint2(l0, l1);
            *(uint2*)(b_p + off)  = make_uint2(packh(pw[i].x, pw[i].y),
                                               packh(pw[i].z, pw[i].w));
        }
    };

    load_regs(0);
    store_regs(0);
    __syncthreads();

    for (int s = 0; s < STAGES; s++) {
        if (s + 1 < STAGES) load_regs(s + 1);
        gemm_stage_compute(sb + (s & 1) * GSTAGE, warp_m, warp_n, lr, lkb, acc);
        if (s + 1 < STAGES) store_regs(((s + 1) & 1) * GSTAGE);
        __syncthreads();
    }

    // ---- epilogue ----
    const int er = lane >> 2;
    const int ec = (lane & 3) * 2;
    if (z == 0) {
#pragma unroll
        for (int mi = 0; mi < 4; mi++)
#pragma unroll
            for (int ni = 0; ni < 4; ni++) {
                const int r = m0 + warp_m * 64 + mi * 16 + er;
                const int c = n0 + warp_n * 32 + ni * 8 + ec;
                uint32_t h, l;
                split2h(acc[mi][ni][0], acc[mi][ni][1], h, l);
                *(uint32_t*)(Qh + (size_t)r * N + c) = h;
                *(uint32_t*)(Ql + (size_t)r * N + c) = l;
                split2h(acc[mi][ni][2], acc[mi][ni][3], h, l);
                *(uint32_t*)(Qh + (size_t)(r + 8) * N + c) = h;
                *(uint32_t*)(Ql + (size_t)(r + 8) * N + c) = l;
            }
    } else {
        __half* C = (z == 1) ? Kv : Vv;
#pragma unroll
        for (int mi = 0; mi < 4; mi++)
#pragma unroll
            for (int ni = 0; ni < 4; ni++) {
                const int r = m0 + warp_m * 64 + mi * 16 + er;
                const int c = n0 + warp_n * 32 + ni * 8 + ec;
                *(uint32_t*)(C + (size_t)r * N + c) =
                    packh(acc[mi][ni][0], acc[mi][ni][1]);
                *(uint32_t*)(C + (size_t)(r + 8) * N + c) =
                    packh(acc[mi][ni][2], acc[mi][ni][3]);
            }
    }
}

// ===========================================================================
// gemm_out: out[M,N] = X @ Wo^T. X = fp16 split pair (copied), Wo f32
// (converted in producer). f32 output.
// ===========================================================================
__global__ __launch_bounds__(256, 1)
void gemm_out(const __half* __restrict__ Xh, const __half* __restrict__ Xl,
              const float* __restrict__ Wo, float* __restrict__ out)
{
    extern __shared__ char smc[];
    const uint32_t sb = smem_u32(smc);
    const int tid  = threadIdx.x;
    const int wid  = tid >> 5;
    const int lane = tid & 31;
    const int warp_m = wid & 1;
    const int warp_n = wid >> 1;
    const int m0 = blockIdx.y * 128;
    const int n0 = blockIdx.x * 128;
    const int K  = D_DIM, N = D_DIM;

    const __half* Ahb = Xh + (size_t)m0 * K;
    const __half* Alb = Xl + (size_t)m0 * K;
    const float*  Wb  = Wo + (size_t)n0 * K;

    float acc[4][4][4];
#pragma unroll
    for (int mi = 0; mi < 4; mi++)
#pragma unroll
        for (int ni = 0; ni < 4; ni++)
#pragma unroll
            for (int q = 0; q < 4; q++) acc[mi][ni][q] = 0.f;

    const int lr  = lane & 15;
    const int lkb = (lane >> 4) << 4;

    uint4 ph[4], pl[4];
    float4 pw[8];
    auto load_regs = [&](int s) {
#pragma unroll
        for (int i = 0; i < 4; i++) {
            const int c = i * 256 + tid;       // 0..1023 over 128x8 chunks
            const int row = c >> 3, ch = c & 7;
            ph[i] = *(const uint4*)(Ahb + (size_t)row * K + s * 64 + ch * 8);
            pl[i] = *(const uint4*)(Alb + (size_t)row * K + s * 64 + ch * 8);
        }
#pragma unroll
        for (int i = 0; i < 8; i++) {
            const int c = i * 256 + tid;
            const int row = c >> 4, ch = c & 15;
            pw[i] = *(const float4*)(Wb + (size_t)row * K + s * 64 + ch * 4);
        }
    };
    auto store_regs = [&](uint32_t bufo) {
        char* hi_p = smc + bufo;
        char* lo_p = smc + bufo + GT;
        char* b_p  = smc + bufo + 2 * GT;
#pragma unroll
        for (int i = 0; i < 4; i++) {
            const int c = i * 256 + tid;
            const int row = c >> 3, ch = c & 7;
            const uint32_t off = row * SASB + ch * 16;
            *(uint4*)(hi_p + off) = ph[i];
            *(uint4*)(lo_p + off) = pl[i];
        }
#pragma unroll
        for (int i = 0; i < 8; i++) {
            const int c = i * 256 + tid;
            const int row = c >> 4, ch = c & 15;
            *(uint2*)(b_p + row * SASB + ch * 8) =
                make_uint2(packh(pw[i].x, pw[i].y), packh(pw[i].z, pw[i].w));
        }
    };

    load_regs(0);
    store_regs(0);
    __syncthreads();

    for (int s = 0; s < STAGES; s++) {
        if (s + 1 < STAGES) load_regs(s + 1);
        gemm_stage_compute(sb + (s & 1) * GSTAGE, warp_m, warp_n, lr, lkb, acc);
        if (s + 1 < STAGES) store_regs(((s + 1) & 1) * GSTAGE);
        __syncthreads();
    }

    const int er = lane >> 2;
    const int ec = (lane & 3) * 2;
#pragma unroll
    for (int mi = 0; mi < 4; mi++)
#pragma unroll
        for (int ni = 0; ni < 4; ni++) {
            const int r = m0 + warp_m * 64 + mi * 16 + er;
            const int c = n0 + warp_n * 32 + ni * 8 + ec;
            *(float2*)(out + (size_t)r * N + c) =
                make_float2(acc[mi][ni][0], acc[mi][ni][1]);
            *(float2*)(out + (size_t)(r + 8) * N + c) =
                make_float2(acc[mi][ni][2], acc[mi][ni][3]);
        }
}

// ===========================================================================
// Flash attention (causal), fp16 operands. CTA = 128 q-rows x (b,h), 8 warps.
// (byte-identical to passing Round-6 kernel)
// ===========================================================================
constexpr int FQHI = 0;
constexpr int FQLO = FQHI + GT;            // 18432
constexpr int FKV0 = FQLO + GT;            // 36864
constexpr int KVT  = 64 * SASB;            // 9216 per 64-row tile
constexpr int KVBUF = 2 * KVT;             // 18432 (K, V)
constexpr int FSM_TOTAL = FKV0 + 2 * KVBUF;  // 73728

__global__ __launch_bounds__(256, 1)
void flash_mma(const __half* __restrict__ Qh, const __half* __restrict__ Ql,
               const __half* __restrict__ Kv, const __half* __restrict__ Vv,
               __half* __restrict__ Xh, __half* __restrict__ Xl)
{
    extern __shared__ char smc[];
    const uint32_t sb = smem_u32(smc);
    const int tid  = threadIdx.x;
    const int wid  = tid >> 5;
    const int lane = tid & 31;
    const int qb   = gridDim.x - 1 - blockIdx.x;   // longest blocks first
    const int h    = blockIdx.y;
    const int b    = blockIdx.z;

    const size_t head = (size_t)b * S_LEN * D_DIM + (size_t)h * DKH;
    const int prow = tid >> 3;
    const int pch  = tid & 7;

    {
        const __half* qb_[2] = {Qh + head, Ql + head};
#pragma unroll
        for (int i = 0; i < 8; i++) {
            const int t   = i >> 2;
            const int row = ((i & 3) << 5) | prow;
            const void* src = qb_[t] + (size_t)(qb * 128 + row) * D_DIM + pch * 8;
            cpasync16(sb + t * GT + row * SASB + pch * 16, src);
        }
    }

    const __half* kvb[2] = {Kv + head, Vv + head};
    auto produce_kv = [&](int kb) {
        const uint32_t bufb = sb + FKV0 + (kb & 1) * KVBUF;
#pragma unroll
        for (int i = 0; i < 4; i++) {
            const int t   = i >> 1;
            const int row = ((i & 1) << 5) | prow;
            const void* src = kvb[t] + (size_t)(kb * 64 + row) * D_DIM + pch * 8;
            cpasync16(bufb + t * KVT + row * SASB + pch * 16, src);
        }
    };

    produce_kv(0);
    cp_commit();

    float o[8][4];
    float m0r = -1e30f, m1r = -1e30f, l0r = 0.f, l1r = 0.f;
#pragma unroll
    for (int ni = 0; ni < 8; ni++)
#pragma unroll
        for (int q = 0; q < 4; q++) o[ni][q] = 0.f;

    const int lr  = lane & 15;
    const int lkb = (lane >> 4) << 4;
    const int kb_max = 2 * qb + 1;

    for (int kb = 0; kb <= kb_max; kb++) {
        if (kb < kb_max) {
            produce_kv(kb + 1);
            cp_commit();
            cp_wait1();
        } else {
            cp_wait0();
        }
        __syncthreads();

        const uint32_t kvbase = sb + FKV0 + (kb & 1) * KVBUF;

        float sc[8][4];
#pragma unroll
        for (int ni = 0; ni < 8; ni++)
#pragma unroll
            for (int q = 0; q < 4; q++) sc[ni][q] = 0.f;

#pragma unroll
        for (int ks = 0; ks < 4; ks++) {
            const uint32_t abyte = (wid * 16 + lr) * SASB + ks * 32 + lkb;
            uint32_t qh[4], ql[4];
            ldmx4(qh, sb + FQHI + abyte);
            ldmx4(ql, sb + FQLO + abyte);
#pragma unroll
            for (int nb = 0; nb < 4; nb++) {
                const uint32_t bbyte = (nb * 16 + lr) * SASB + ks * 32 + lkb;
                uint32_t kh[4];
                ldmx4(kh, kvbase + bbyte);
                mma16816(sc[nb * 2],     qh, kh[0], kh[2]);
                mma16816(sc[nb * 2],     ql, kh[0], kh[2]);
                mma16816(sc[nb * 2 + 1], qh, kh[1], kh[3]);
                mma16816(sc[nb * 2 + 1], ql, kh[1], kh[3]);
            }
        }

#pragma unroll
        for (int ni = 0; ni < 8; ni++)
#pragma unroll
            for (int q = 0; q < 4; q++) sc[ni][q] *= 0.125f;

        const int q0 = qb * 128 + wid * 16 + (lane >> 2);
        if (kb * 64 + 63 > qb * 128 + wid * 16) {
#pragma unroll
            for (int ni = 0; ni < 8; ni++) {
#pragma unroll
                for (int c = 0; c < 2; c++) {
                    const int col = kb * 64 + ni * 8 + (lane & 3) * 2 + c;
                    if (col > q0)     sc[ni][c]     = -1e30f;
                    if (col > q0 + 8) sc[ni][2 + c] = -1e30f;
                }
            }
        }

        float mx0 = -1e30f, mx1 = -1e30f;
#pragma unroll
        for (int ni = 0; ni < 8; ni++) {
            mx0 = fmaxf(mx0, fmaxf(sc[ni][0], sc[ni][1]));
            mx1 = fmaxf(mx1, fmaxf(sc[ni][2], sc[ni][3]));
        }
        mx0 = fmaxf(mx0, __shfl_xor_sync(0xffffffffu, mx0, 1));
        mx0 = fmaxf(mx0, __shfl_xor_sync(0xffffffffu, mx0, 2));
        mx1 = fmaxf(mx1, __shfl_xor_sync(0xffffffffu, mx1, 1));
        mx1 = fmaxf(mx1, __shfl_xor_sync(0xffffffffu, mx1, 2));

        const float mn0 = fmaxf(m0r, mx0);
        const float mn1 = fmaxf(m1r, mx1);
        const float al0 = __expf(m0r - mn0);
        const float al1 = __expf(m1r - mn1);
        m0r = mn0; m1r = mn1;

        float ls0 = 0.f, ls1 = 0.f;
#pragma unroll
        for (int ni = 0; ni < 8; ni++) {
            sc[ni][0] = __expf(sc[ni][0] - mn0); ls0 += sc[ni][0];
            sc[ni][1] = __expf(sc[ni][1] - mn0); ls0 += sc[ni][1];
            sc[ni][2] = __expf(sc[ni][2] - mn1); ls1 += sc[ni][2];
            sc[ni][3] = __expf(sc[ni][3] - mn1); ls1 += sc[ni][3];
        }
        ls0 += __shfl_xor_sync(0xffffffffu, ls0, 1);
        ls0 += __shfl_xor_sync(0xffffffffu, ls0, 2);
        ls1 += __shfl_xor_sync(0xffffffffu, ls1, 1);
        ls1 += __shfl_xor_sync(0xffffffffu, ls1, 2);
        l0r = l0r * al0 + ls0;
        l1r = l1r * al1 + ls1;
#pragma unroll
        for (int ni = 0; ni < 8; ni++) {
            o[ni][0] *= al0; o[ni][1] *= al0;
            o[ni][2] *= al1; o[ni][3] *= al1;
        }

#pragma unroll
        for (int ks = 0; ks < 4; ks++) {
            uint32_t ph[4], pl[4];
            split2h(sc[2 * ks][0],     sc[2 * ks][1],     ph[0], pl[0]);
            split2h(sc[2 * ks][2],     sc[2 * ks][3],     ph[1], pl[1]);
            split2h(sc[2 * ks + 1][0], sc[2 * ks + 1][1], ph[2], pl[2]);
            split2h(sc[2 * ks + 1][2], sc[2 * ks + 1][3], ph[3], pl[3]);
#pragma unroll
            for (int nt = 0; nt < 4; nt++) {
                const uint32_t vbyte =
                    (ks * 16 + ((lane >> 3) & 1) * 8 + (lane & 7)) * SASB +
                    nt * 32 + ((lane >> 4) << 4);
                uint32_t vh[4];
                ldmx4t(vh, kvbase + KVT + vbyte);
                mma16816(o[nt * 2],     ph, vh[0], vh[1]);
                mma16816(o[nt * 2],     pl, vh[0], vh[1]);
                mma16816(o[nt * 2 + 1], ph, vh[2], vh[3]);
                mma16816(o[nt * 2 + 1], pl, vh[2], vh[3]);
            }
        }
        __syncthreads();
    }

    const float inv0 = 1.f / l0r;
    const float inv1 = 1.f / l1r;
    const int r0 = qb * 128 + wid * 16 + (lane >> 2);
    const int ec = (lane & 3) * 2;
#pragma unroll
    for (int ni = 0; ni < 8; ni++) {
        const size_t c = head + (size_t)ni * 8 + ec;
        uint32_t hh, ll;
        split2h(o[ni][0] * inv0, o[ni][1] * inv0, hh, ll);
        *(uint32_t*)(Xh + c + (size_t)r0 * D_DIM) = hh;
        *(uint32_t*)(Xl + c + (size_t)r0 * D_DIM) = ll;
        split2h(o[ni][2] * inv1, o[ni][3] * inv1, hh, ll);
        *(uint32_t*)(Xh + c + (size_t)(r0 + 8) * D_DIM) = hh;
        *(uint32_t*)(Xl + c + (size_t)(r0 + 8) * D_DIM) = ll;
    }
}

// ---------------------------------------------------------------------------
// launch
// ---------------------------------------------------------------------------
extern "C" void kernel_launch(void* const* d_in, const int* in_sizes, int n_in,
                              void* d_out, int out_size)
{
    const float* query = (const float*)d_in[0];
    const float* key   = (const float*)d_in[1];
    const float* value = (const float*)d_in[2];
    const float* Wq    = (const float*)d_in[3];
    const float* Wk    = (const float*)d_in[4];
    const float* Wv    = (const float*)d_in[5];
    const float* Wo    = (const float*)d_in[6];
    float* out = (float*)d_out;

    __half *Qh, *Ql, *Kv, *Vv, *Xh, *Xl;
    cudaGetSymbolAddress((void**)&Qh, g_Qh); cudaGetSymbolAddress((void**)&Ql, g_Ql);
    cudaGetSymbolAddress((void**)&Kv, g_Kv); cudaGetSymbolAddress((void**)&Vv, g_Vv);
    cudaGetSymbolAddress((void**)&Xh, g_Xh); cudaGetSymbolAddress((void**)&Xl, g_Xl);

    cudaFuncSetAttribute(gemm_proj, cudaFuncAttributeMaxDynamicSharedMemorySize,
                         SM_GEMM_TOTAL);
    cudaFuncSetAttribute(gemm_out, cudaFuncAttributeMaxDynamicSharedMemorySize,
                         SM_GEMM_TOTAL);
    cudaFuncSetAttribute(flash_mma, cudaFuncAttributeMaxDynamicSharedMemorySize,
                         FSM_TOTAL);

    dim3 pgrid(D_DIM / 128, MTOT / 128, 3);   // (8, 32, 3)
    gemm_proj<<<pgrid, 256, SM_GEMM_TOTAL>>>(query, key, value, Wq, Wk, Wv,
                                             Qh, Ql, Kv, Vv);

    dim3 fgrid(S_LEN / 128, H_NUM, B_SZ);     // (16, 16, 2)
    flash_mma<<<fgrid, 256, FSM_TOTAL>>>(Qh, Ql, Kv, Vv, Xh, Xl);

    dim3 ogrid(D_DIM / 128, MTOT / 128);      // (8, 32)
    gemm_out<<<ogrid, 256, SM_GEMM_TOTAL>>>(Xh, Xl, Wo, out);
}